// round 3
// baseline (speedup 1.0000x reference)
#include <cuda_runtime.h>

// Batched 12-qubit real statevector simulator, 1 warp per batch element.
// State bits: [11..7] = lane id bits, [6..0] = per-thread register index.
// Encoding layer folded into product-state init; final CNOT ring folded into
// GF(2) prefix-parity measurement masks; variational RYs in tan-half-angle
// form (uniform scale factored out). No smem, no block barriers.

#define FULLMASK 0xFFFFFFFFu
constexpr int NQ    = 12;
constexpr int RB    = 7;        // register bits
constexpr int NREG  = 128;      // amplitudes per thread
constexpr int BATCH = 1024;

// <Z_q> = sum_u p(u) * (-1)^popc(u & MASKS[q])  (last CNOT ring folded in):
// psi_final(u) = psi0(K(u)), K = F0∘F1∘...∘F11; bit_q(K^{-1}(u)) is the
// prefix parity of u's bits: q=0 -> bits 1..11, q=k -> bits 0..k.
__device__ constexpr int MASKS[NQ] = {
    0xFFE, 0x003, 0x007, 0x00F, 0x01F, 0x03F,
    0x07F, 0x0FF, 0x1FF, 0x3FF, 0x7FF, 0xFFF
};

// RY in tan form: [[1,-t],[t,1]] (true gate = c * this; c accumulated outside)
template<int Q>
__device__ __forceinline__ void ry_gate_t(float (&a)[NREG], float t, int lane)
{
    if constexpr (Q < RB) {
        constexpr int m = 1 << Q;
#pragma unroll
        for (int r = 0; r < NREG; r++) {
            if ((r & m) == 0) {
                float a0 = a[r], a1 = a[r | m];
                a[r]     = fmaf(-t, a1, a0);   // 1 FFMA
                a[r | m] = fmaf( t, a0, a1);   // 1 FFMA
            }
        }
    } else {
        constexpr int lm = 1 << (Q - RB);
        float sg = (lane & lm) ? t : -t;
#pragma unroll
        for (int r = 0; r < NREG; r++) {
            float other = __shfl_xor_sync(FULLMASK, a[r], lm);
            a[r] = fmaf(sg, other, a[r]);      // 1 SHFL + 1 FFMA
        }
    }
}

template<int C, int T>
__device__ __forceinline__ void cnot_gate(float (&a)[NREG], int lane)
{
    if constexpr (C < RB && T < RB) {
        // both bits register-resident: compile-time permutation (free renames)
        constexpr int cm = 1 << C, tm = 1 << T;
#pragma unroll
        for (int r = 0; r < NREG; r++) {
            if ((r & cm) && !(r & tm)) {
                float tmp = a[r]; a[r] = a[r | tm]; a[r | tm] = tmp;
            }
        }
    } else if constexpr (C < RB && T >= RB) {
        // control in registers, target across lanes: shuffle control=1 regs only
        constexpr int cm = 1 << C, lm = 1 << (T - RB);
#pragma unroll
        for (int r = 0; r < NREG; r++) {
            if (r & cm) a[r] = __shfl_xor_sync(FULLMASK, a[r], lm);
        }
    } else if constexpr (C >= RB && T < RB) {
        // control on lane bit, target in registers: predicated register swap
        constexpr int tm = 1 << T;
        bool sw = (lane & (1 << (C - RB))) != 0;
#pragma unroll
        for (int r = 0; r < NREG; r++) {
            if (!(r & tm)) {
                float t0 = a[r], t1 = a[r | tm];
                a[r]      = sw ? t1 : t0;
                a[r | tm] = sw ? t0 : t1;
            }
        }
    } else {
        // both on lane bits: shuffle + select
        constexpr int lm = 1 << (T - RB);
        bool sw = (lane & (1 << (C - RB))) != 0;
#pragma unroll
        for (int r = 0; r < NREG; r++) {
            float other = __shfl_xor_sync(FULLMASK, a[r], lm);
            a[r] = sw ? other : a[r];
        }
    }
}

__global__ void __launch_bounds__(128)
qcircuit_kernel(const float* __restrict__ x,
                const float* __restrict__ th,
                float* __restrict__ out)
{
    const int lane = threadIdx.x & 31;
    const int b    = blockIdx.x * 4 + (threadIdx.x >> 5);

    float a[NREG];

    // ---- encoding layer folded into product-state construction ----
    // amplitude(i) = prod_q (bit_q(i) ? sin(x_q/2) : cos(x_q/2))
    // (direct form here: x ~ N(0,1) so tan(x/2) can be ill-conditioned)
    const float* xb = x + b * NQ;
    float cw[RB], sw[RB];
    float lp = 1.0f;
#pragma unroll
    for (int q = 0; q < NQ; q++) {
        float s, c;
        __sincosf(0.5f * xb[q], &s, &c);
        if (q < RB) { cw[q] = c; sw[q] = s; }
        else        lp *= (lane & (1 << (q - RB))) ? s : c;
    }
    a[0] = lp;
#pragma unroll
    for (int j = 0; j < RB; j++) {
#pragma unroll
        for (int r = 0; r < (1 << j); r++) {
            a[r | (1 << j)] = a[r] * sw[j];
            a[r]            = a[r] * cw[j];
        }
    }

    // ---- variational RYs in tan form; accumulate uniform scale ----
    // thetas = 0.1*N(0,1) -> |theta/2| <= ~0.3, c ~ 1: tan form is safe.
    float scale = 1.0f;
#define RYQ(Q, TBASE) { float s_, c_;                                    \
        __sincosf(0.5f * th[(TBASE) + (Q)], &s_, &c_);                   \
        scale *= c_;                                                     \
        ry_gate_t<Q>(a, __fdividef(s_, c_), lane); }

    // ---- layer 0: RY(theta[0,q]) + full CNOT ring ----
    RYQ(0, 0)  RYQ(1, 0)  RYQ(2, 0)  RYQ(3, 0)  RYQ(4, 0)  RYQ(5, 0)
    RYQ(6, 0)  RYQ(7, 0)  RYQ(8, 0)  RYQ(9, 0)  RYQ(10, 0) RYQ(11, 0)

    cnot_gate<0, 1>(a, lane);   cnot_gate<1, 2>(a, lane);
    cnot_gate<2, 3>(a, lane);   cnot_gate<3, 4>(a, lane);
    cnot_gate<4, 5>(a, lane);   cnot_gate<5, 6>(a, lane);
    cnot_gate<6, 7>(a, lane);   cnot_gate<7, 8>(a, lane);
    cnot_gate<8, 9>(a, lane);   cnot_gate<9, 10>(a, lane);
    cnot_gate<10, 11>(a, lane); cnot_gate<11, 0>(a, lane);

    // ---- layer 1: RY(theta[1,q]); its CNOT ring is folded into MASKS ----
    RYQ(0, NQ)  RYQ(1, NQ)  RYQ(2, NQ)  RYQ(3, NQ)  RYQ(4, NQ)  RYQ(5, NQ)
    RYQ(6, NQ)  RYQ(7, NQ)  RYQ(8, NQ)  RYQ(9, NQ)  RYQ(10, NQ) RYQ(11, NQ)

#undef RYQ

    // ---- measurement epilogue ----
    // Register-bit parts of the 12 masks collapse to 7 distinct masks:
    //   q0 -> 0x7E, q1..q6 -> prefix masks, q7..q11 -> 0x7F (same as q6).
    constexpr int RMASK[7] = { 0x7E, 0x03, 0x07, 0x0F, 0x1F, 0x3F, 0x7F };
    float acc[7];
#pragma unroll
    for (int i = 0; i < 7; i++) acc[i] = 0.0f;
#pragma unroll
    for (int r = 0; r < NREG; r++) {
        float p = a[r] * a[r];
#pragma unroll
        for (int i = 0; i < 7; i++)
            acc[i] += (__popc(r & RMASK[i]) & 1) ? -p : p;   // sign folded at compile time
    }

    // restore the factored-out gate scale: probs scale by scale^2
    const float s2 = scale * scale;
#pragma unroll
    for (int i = 0; i < 7; i++) acc[i] *= s2;

    // apply lane-bit parity signs per qubit
    float e[NQ];
#pragma unroll
    for (int q = 0; q < NQ; q++) {
        const int lm = MASKS[q] >> RB;
        const int ai = (q == 0) ? 0 : (q <= 6 ? q : 6);
        float v = acc[ai];
        e[q] = (__popc(lane & lm) & 1) ? -v : v;
    }

    // warp-level butterfly reduction of the 12 expectations
#pragma unroll
    for (int q = 0; q < NQ; q++) {
#pragma unroll
        for (int off = 16; off > 0; off >>= 1)
            e[q] += __shfl_xor_sync(FULLMASK, e[q], off);
    }

    if (lane == 0) {
        // 12 floats = 48 bytes, row base is 16B-aligned -> 3x STG.128
        float4* o = (float4*)(out + b * NQ);
        o[0] = make_float4(e[0], e[1], e[2],  e[3]);
        o[1] = make_float4(e[4], e[5], e[6],  e[7]);
        o[2] = make_float4(e[8], e[9], e[10], e[11]);
    }
}

extern "C" void kernel_launch(void* const* d_in, const int* in_sizes, int n_in,
                              void* d_out, int out_size)
{
    const float* x  = (const float*)d_in[0];   // (1024, 12) f32
    const float* th = (const float*)d_in[1];   // (2, 12)   f32
    float* out = (float*)d_out;                // (1024, 12) f32

    // 1 warp per batch element: 1024 warps = 256 blocks x 128 threads
    qcircuit_kernel<<<BATCH / 4, 128>>>(x, th, out);
}

// round 4
// speedup vs baseline: 1.1732x; 1.1732x over previous
#include <cuda_runtime.h>

// Batched 12-qubit real statevector simulator, 1 warp per batch element.
// State bits: [11..7] = lane id bits, [6..0] = per-thread register index.
// Encoding folded into product-state init. BOTH CNOT rings are never applied:
//  - ring 1 is folded into layer-1 RY gates via a GF(2) index relabeling
//    (gate mask m_q = M e_q, sign mask w_q = row q of M^-1),
//  - ring 2 (+ the relabeling) is folded into the measurement masks.
// No smem, no block barriers, pure FFMA + SHFL.

#define FULLMASK 0xFFFFFFFFu
constexpr int NQ    = 12;
constexpr int RB    = 7;        // register bits
constexpr int NREG  = 128;      // amplitudes per thread
constexpr int BATCH = 1024;

// compile-time parity
__device__ __host__ __forceinline__ constexpr int cpar(int x)
{
    x ^= x >> 8; x ^= x >> 4; x ^= x >> 2; x ^= x >> 1;
    return x & 1;
}

// ---------------- layer-0 RY (identity relabeling), tan form ----------------
// RY = c*[[1,-t],[t,1]]; uniform c factored out into `scale`.
template<int Q>
__device__ __forceinline__ void ry0_gate(float (&a)[NREG], float t, int lane)
{
    if constexpr (Q < RB) {
        constexpr int m = 1 << Q;
#pragma unroll
        for (int r = 0; r < NREG; r++) {
            if ((r & m) == 0) {
                float a0 = a[r], a1 = a[r | m];
                a[r]     = fmaf(-t, a1, a0);
                a[r | m] = fmaf( t, a0, a1);
            }
        }
    } else {
        constexpr int lm = 1 << (Q - RB);
        float sg = (lane & lm) ? t : -t;
#pragma unroll
        for (int r = 0; r < NREG; r++) {
            float other = __shfl_xor_sync(FULLMASK, a[r], lm);
            a[r] = fmaf(sg, other, a[r]);
        }
    }
}

// ---------------- layer-1 RY under relabeling u -> M u ----------------
// Pair: (u, u^m); element with logical bit 1 has parity(u & w) == 1.
// new a[u] = a[u] + s(u)*t*a[u^m], s = +1 if parity(u&w) else -1.
template<int MREG, int WREG, int WLANE>
__device__ __forceinline__ void ry1_reg(float (&a)[NREG], float t, int lane)
{
    constexpr int LB = MREG & (-MREG);
    const float tl = (__popc(lane & WLANE) & 1) ? t : -t;
#pragma unroll
    for (int r = 0; r < NREG; r++) {
        if ((r & LB) == 0) {
            const int r2 = r ^ MREG;
            const float t0 = cpar(r & WREG) ? -tl : tl;   // compile-time sign pick
            float a0 = a[r], a1 = a[r2];
            a[r]  = fmaf( t0, a1, a0);
            a[r2] = fmaf(-t0, a0, a1);
        }
    }
}

template<int MREG, int MLANE, int WREG, int WLANE>
__device__ __forceinline__ void ry1_lane(float (&a)[NREG], float t, int lane)
{
    const float tl = (__popc(lane & WLANE) & 1) ? t : -t;
    if constexpr (MREG == 0) {
#pragma unroll
        for (int r = 0; r < NREG; r++) {
            float other = __shfl_xor_sync(FULLMASK, a[r], MLANE);
            const float t0 = cpar(r & WREG) ? -tl : tl;
            a[r] = fmaf(t0, other, a[r]);
        }
    } else {
        // mixed reg+lane mask: fetch both pair halves before overwriting
        constexpr int LB = MREG & (-MREG);
#pragma unroll
        for (int r = 0; r < NREG; r++) {
            if ((r & LB) == 0) {
                const int r2 = r ^ MREG;
                float ohi = __shfl_xor_sync(FULLMASK, a[r2], MLANE);
                float olo = __shfl_xor_sync(FULLMASK, a[r],  MLANE);
                const float t0 = cpar(r  & WREG) ? -tl : tl;
                const float t2 = cpar(r2 & WREG) ? -tl : tl;
                a[r]  = fmaf(t0, ohi, a[r]);
                a[r2] = fmaf(t2, olo, a[r2]);
            }
        }
    }
}

__global__ void __launch_bounds__(32)
qcircuit_kernel(const float* __restrict__ x,
                const float* __restrict__ th,
                float* __restrict__ out)
{
    const int lane = threadIdx.x;
    const int b    = blockIdx.x;

    float a[NREG];

    // ---- encoding layer folded into product-state construction ----
    // amplitude(i) = prod_q (bit_q(i) ? sin(x_q/2) : cos(x_q/2))
    const float* xb = x + b * NQ;
    float cw[RB], sw[RB];
    float lp = 1.0f;
#pragma unroll
    for (int q = 0; q < NQ; q++) {
        float s, c;
        __sincosf(0.5f * xb[q], &s, &c);
        if (q < RB) { cw[q] = c; sw[q] = s; }
        else        lp *= (lane & (1 << (q - RB))) ? s : c;
    }
    a[0] = lp;
#pragma unroll
    for (int j = 0; j < RB; j++) {
#pragma unroll
        for (int r = 0; r < (1 << j); r++) {
            a[r | (1 << j)] = a[r] * sw[j];
            a[r]            = a[r] * cw[j];
        }
    }

    // tan-half-angle for variational gates (|theta|~0.1 -> well conditioned)
    float scale = 1.0f;
#define TANQ(Q, TBASE, t_) float t_;                                     \
    { float s_, c_;                                                      \
      __sincosf(0.5f * th[(TBASE) + (Q)], &s_, &c_);                     \
      scale *= c_;  t_ = __fdividef(s_, c_); }

    // ---- layer 0: plain RY(theta[0,q]) ----
    { TANQ(0, 0, t) ry0_gate<0>(a, t, lane); }
    { TANQ(1, 0, t) ry0_gate<1>(a, t, lane); }
    { TANQ(2, 0, t) ry0_gate<2>(a, t, lane); }
    { TANQ(3, 0, t) ry0_gate<3>(a, t, lane); }
    { TANQ(4, 0, t) ry0_gate<4>(a, t, lane); }
    { TANQ(5, 0, t) ry0_gate<5>(a, t, lane); }
    { TANQ(6, 0, t) ry0_gate<6>(a, t, lane); }
    { TANQ(7, 0, t) ry0_gate<7>(a, t, lane); }
    { TANQ(8, 0, t) ry0_gate<8>(a, t, lane); }
    { TANQ(9, 0, t) ry0_gate<9>(a, t, lane); }
    { TANQ(10,0, t) ry0_gate<10>(a, t, lane); }
    { TANQ(11,0, t) ry0_gate<11>(a, t, lane); }

    // ---- CNOT ring 1: folded into layer-1 gate masks (zero cost) ----
    // M = P0*P1*...*P11; columns M e_q: q0->0x003, qk->3<<k (k=1..10), q11->0x803
    // rows of M^-1 (sign masks): w0=0xFFE, wq=(1<<(q+1))-1.

    // ---- layer 1: RY(theta[1,q]) on relabeled pairs ----
    { TANQ(0, NQ, t) ry1_reg <0x03,       0x7E, 0x1F>(a, t, lane); }
    { TANQ(1, NQ, t) ry1_reg <0x06,       0x03, 0x00>(a, t, lane); }
    { TANQ(2, NQ, t) ry1_reg <0x0C,       0x07, 0x00>(a, t, lane); }
    { TANQ(3, NQ, t) ry1_reg <0x18,       0x0F, 0x00>(a, t, lane); }
    { TANQ(4, NQ, t) ry1_reg <0x30,       0x1F, 0x00>(a, t, lane); }
    { TANQ(5, NQ, t) ry1_reg <0x60,       0x3F, 0x00>(a, t, lane); }
    { TANQ(6, NQ, t) ry1_lane<0x40, 0x01, 0x7F, 0x00>(a, t, lane); }
    { TANQ(7, NQ, t) ry1_lane<0x00, 0x03, 0x7F, 0x01>(a, t, lane); }
    { TANQ(8, NQ, t) ry1_lane<0x00, 0x06, 0x7F, 0x03>(a, t, lane); }
    { TANQ(9, NQ, t) ry1_lane<0x00, 0x0C, 0x7F, 0x07>(a, t, lane); }
    { TANQ(10,NQ, t) ry1_lane<0x00, 0x18, 0x7F, 0x0F>(a, t, lane); }
    { TANQ(11,NQ, t) ry1_lane<0x03, 0x10, 0x7F, 0x1F>(a, t, lane); }
#undef TANQ

    // ---- measurement: masks re-folded through M^-1 (ring2 + relabeling) ----
    // MASK'_q = M^-T * prefix-mask_q:
    //  q : 0     1     2     3     4     5     6     7     8     9     10    11
    //  m : 0xAAB 0xFFD 0xFFA 0xFF5 0xFEA 0xFD5 0xFAA 0xF55 0xEAA 0xD55 0xAAA 0x555
    // Register parts collapse to 7 distinct masks:
    constexpr int RMASK[7] = { 0x2B, 0x7D, 0x7A, 0x75, 0x6A, 0x55, 0x2A };
    // qubit -> (acc index, lane-parity mask)
    constexpr int ACCIDX[NQ] = { 0, 1, 2, 3, 4, 5, 6, 5, 6, 5, 6, 5 };
    constexpr int LMASK[NQ]  = { 0x15, 0x1F, 0x1F, 0x1F, 0x1F, 0x1F,
                                 0x1F, 0x1E, 0x1D, 0x1A, 0x15, 0x0A };

    float acc[7];
#pragma unroll
    for (int i = 0; i < 7; i++) acc[i] = 0.0f;
#pragma unroll
    for (int r = 0; r < NREG; r++) {
        float p = a[r] * a[r];
#pragma unroll
        for (int i = 0; i < 7; i++)
            acc[i] += cpar(r & RMASK[i]) ? -p : p;   // sign folded at compile time
    }

    // restore factored-out gate scale (probs scale by scale^2)
    const float s2 = scale * scale;
#pragma unroll
    for (int i = 0; i < 7; i++) acc[i] *= s2;

    // per-qubit lane-parity sign, then warp butterfly reduction
    float e[NQ];
#pragma unroll
    for (int q = 0; q < NQ; q++) {
        float v = acc[ACCIDX[q]];
        e[q] = (__popc(lane & LMASK[q]) & 1) ? -v : v;
    }
#pragma unroll
    for (int q = 0; q < NQ; q++) {
#pragma unroll
        for (int off = 16; off > 0; off >>= 1)
            e[q] += __shfl_xor_sync(FULLMASK, e[q], off);
    }

    if (lane == 0) {
        float4* o = (float4*)(out + b * NQ);
        o[0] = make_float4(e[0], e[1], e[2],  e[3]);
        o[1] = make_float4(e[4], e[5], e[6],  e[7]);
        o[2] = make_float4(e[8], e[9], e[10], e[11]);
    }
}

extern "C" void kernel_launch(void* const* d_in, const int* in_sizes, int n_in,
                              void* d_out, int out_size)
{
    const float* x  = (const float*)d_in[0];   // (1024, 12) f32
    const float* th = (const float*)d_in[1];   // (2, 12)   f32
    float* out = (float*)d_out;                // (1024, 12) f32

    // 1 warp per batch element, 1 warp per block for near-perfect wave balance
    qcircuit_kernel<<<BATCH, 32>>>(x, th, out);
}

// round 9
// speedup vs baseline: 1.5970x; 1.3612x over previous
#include <cuda_runtime.h>

// Batched 12-qubit real statevector simulator, 1 warp per batch element.
// State bits: [11..7] = lane id bits, [6..0] = per-thread register index.
//
// Circuit algebra (only 12 physical gates remain):
//  - encoding RY(x_q) and layer-0 RY(th0_q) fuse: RY(a)RY(b)=RY(a+b)
//    -> product-state init with angles (x_q + th0_q)/2.
//  - CNOT ring 1 folded into layer-1 gates via GF(2) relabeling u -> M u
//    (gate mask m_q = M e_q, sign mask w_q = row q of M^-1).
//  - CNOT ring 2 + relabeling folded into measurement parity masks.
//  - epilogue = 2-level partial Walsh-Hadamard + 7 parity sums.
// No smem, no barriers: pure FFMA + SHFL.

#define FULLMASK 0xFFFFFFFFu
constexpr int NQ    = 12;
constexpr int RB    = 7;        // register bits
constexpr int NREG  = 128;      // amplitudes per thread
constexpr int BATCH = 1024;

// compile-time parity
__device__ __host__ __forceinline__ constexpr int cpar(int x)
{
    x ^= x >> 8; x ^= x >> 4; x ^= x >> 2; x ^= x >> 1;
    return x & 1;
}

// ---------------- layer-1 RY under relabeling u -> M u, tan form ----------------
// Pair (u, u^m); logical-1 element has parity(u & w) == 1.
// new a[u] = a[u] + s(u)*t*a[u^m], s = +1 if parity(u&w) else -1.
template<int MREG, int WREG, int WLANE>
__device__ __forceinline__ void ry1_reg(float (&a)[NREG], float t, int lane)
{
    constexpr int LB = MREG & (-MREG);
    const float tl = (__popc(lane & WLANE) & 1) ? t : -t;
#pragma unroll
    for (int r = 0; r < NREG; r++) {
        if ((r & LB) == 0) {
            const int r2 = r ^ MREG;
            const float t0 = cpar(r & WREG) ? -tl : tl;   // compile-time sign pick
            float a0 = a[r], a1 = a[r2];
            a[r]  = fmaf( t0, a1, a0);
            a[r2] = fmaf(-t0, a0, a1);
        }
    }
}

template<int MREG, int MLANE, int WREG, int WLANE>
__device__ __forceinline__ void ry1_lane(float (&a)[NREG], float t, int lane)
{
    const float tl = (__popc(lane & WLANE) & 1) ? t : -t;
    if constexpr (MREG == 0) {
#pragma unroll
        for (int r = 0; r < NREG; r++) {
            float other = __shfl_xor_sync(FULLMASK, a[r], MLANE);
            const float t0 = cpar(r & WREG) ? -tl : tl;
            a[r] = fmaf(t0, other, a[r]);
        }
    } else {
        // mixed reg+lane mask: fetch both pair halves before overwriting
        constexpr int LB = MREG & (-MREG);
#pragma unroll
        for (int r = 0; r < NREG; r++) {
            if ((r & LB) == 0) {
                const int r2 = r ^ MREG;
                float ohi = __shfl_xor_sync(FULLMASK, a[r2], MLANE);
                float olo = __shfl_xor_sync(FULLMASK, a[r],  MLANE);
                const float t0 = cpar(r  & WREG) ? -tl : tl;
                const float t2 = cpar(r2 & WREG) ? -tl : tl;
                a[r]  = fmaf(t0, ohi, a[r]);
                a[r2] = fmaf(t2, olo, a[r2]);
            }
        }
    }
}

__global__ void __launch_bounds__(32)
qcircuit_kernel(const float* __restrict__ x,
                const float* __restrict__ th,
                float* __restrict__ out)
{
    const int lane = threadIdx.x;
    const int b    = blockIdx.x;

    float a[NREG];

    // ---- encoding + layer 0 fused into product-state construction ----
    // amplitude(i) = prod_q (bit_q(i) ? sin(ang_q) : cos(ang_q)),
    // ang_q = (x_q + theta0_q)/2   (RY(a)RY(b) = RY(a+b))
    const float* xb = x + b * NQ;
    float cw[RB], sw[RB];
    float lp = 1.0f;
#pragma unroll
    for (int q = 0; q < NQ; q++) {
        float s, c;
        __sincosf(0.5f * (xb[q] + th[q]), &s, &c);
        if (q < RB) { cw[q] = c; sw[q] = s; }
        else        lp *= (lane & (1 << (q - RB))) ? s : c;
    }
    a[0] = lp;
#pragma unroll
    for (int j = 0; j < RB; j++) {
#pragma unroll
        for (int r = 0; r < (1 << j); r++) {
            a[r | (1 << j)] = a[r] * sw[j];
            a[r]            = a[r] * cw[j];
        }
    }

    // ---- layer 1: RY(theta[1,q]) on relabeled pairs, tan-half-angle form ----
    // thetas = 0.1*N(0,1) -> well conditioned; uniform cos factored into scale.
    float scale = 1.0f;
#define TANQ(Q, t_) float t_;                                            \
    { float s_, c_;                                                      \
      __sincosf(0.5f * th[NQ + (Q)], &s_, &c_);                          \
      scale *= c_;  t_ = __fdividef(s_, c_); }

    // M = P0*...*P11; columns M e_q: q0->0x003, qk->3<<k (k=1..10), q11->0x803
    // rows of M^-1 (sign masks): w0=0xFFE, wq=(1<<(q+1))-1.
    { TANQ(0,  t) ry1_reg <0x03,       0x7E, 0x1F>(a, t, lane); }
    { TANQ(1,  t) ry1_reg <0x06,       0x03, 0x00>(a, t, lane); }
    { TANQ(2,  t) ry1_reg <0x0C,       0x07, 0x00>(a, t, lane); }
    { TANQ(3,  t) ry1_reg <0x18,       0x0F, 0x00>(a, t, lane); }
    { TANQ(4,  t) ry1_reg <0x30,       0x1F, 0x00>(a, t, lane); }
    { TANQ(5,  t) ry1_reg <0x60,       0x3F, 0x00>(a, t, lane); }
    { TANQ(6,  t) ry1_lane<0x40, 0x01, 0x7F, 0x00>(a, t, lane); }
    { TANQ(7,  t) ry1_lane<0x00, 0x03, 0x7F, 0x01>(a, t, lane); }
    { TANQ(8,  t) ry1_lane<0x00, 0x06, 0x7F, 0x03>(a, t, lane); }
    { TANQ(9,  t) ry1_lane<0x00, 0x0C, 0x7F, 0x07>(a, t, lane); }
    { TANQ(10, t) ry1_lane<0x00, 0x18, 0x7F, 0x0F>(a, t, lane); }
    { TANQ(11, t) ry1_lane<0x03, 0x10, 0x7F, 0x1F>(a, t, lane); }
#undef TANQ

    // ---- measurement epilogue ----
    // Full masks MASK'_q = M^-T * prefix-mask_q:
    //  q : 0     1     2     3     4     5     6     7     8     9     10    11
    //  m : 0xAAB 0xFFD 0xFFA 0xFF5 0xFEA 0xFD5 0xFAA 0xF55 0xEAA 0xD55 0xAAA 0x555
    // Register parts collapse to 7 masks:
    //   idx: 0=0x2B 1=0x7D 2=0x7A 3=0x75 4=0x6A 5=0x55 6=0x2A
    // 2-level partial WHT over register bits 0,1:
    //   mask bit0 set -> diff at level 1, else sum; same on bit1 at level 2.
    float s1[NREG / 2], d1[NREG / 2];
#pragma unroll
    for (int k = 0; k < NREG / 2; k++) {
        float p0 = a[2 * k] * a[2 * k];
        float p1 = a[2 * k + 1] * a[2 * k + 1];
        s1[k] = p0 + p1;
        d1[k] = p0 - p1;
    }
    float s2d[NREG / 4], d2s[NREG / 4], d2d[NREG / 4];   // s2s never needed
#pragma unroll
    for (int j = 0; j < NREG / 4; j++) {
        s2d[j] = s1[2 * j] - s1[2 * j + 1];
        d2s[j] = d1[2 * j] + d1[2 * j + 1];
        d2d[j] = d1[2 * j] - d1[2 * j + 1];
    }
    // residual masks over j (reg bits 2..6):
    //  0x2B->d2d/0x0A  0x7D->d2s/0x1F  0x7A->s2d/0x1E  0x75->d2s/0x1D
    //  0x6A->s2d/0x1A  0x55->d2s/0x15  0x2A->s2d/0x0A
    float acc[7];
#pragma unroll
    for (int i = 0; i < 7; i++) acc[i] = 0.0f;
#pragma unroll
    for (int j = 0; j < NREG / 4; j++) {
        acc[0] += cpar(j & 0x0A) ? -d2d[j] : d2d[j];
        acc[1] += cpar(j & 0x1F) ? -d2s[j] : d2s[j];
        acc[2] += cpar(j & 0x1E) ? -s2d[j] : s2d[j];
        acc[3] += cpar(j & 0x1D) ? -d2s[j] : d2s[j];
        acc[4] += cpar(j & 0x1A) ? -s2d[j] : s2d[j];
        acc[5] += cpar(j & 0x15) ? -d2s[j] : d2s[j];
        acc[6] += cpar(j & 0x0A) ? -s2d[j] : s2d[j];
    }

    // restore factored-out gate scale (probs scale by scale^2)
    const float s2 = scale * scale;
#pragma unroll
    for (int i = 0; i < 7; i++) acc[i] *= s2;

    // per-qubit (acc index, lane-parity mask), then warp butterfly reduction
    constexpr int ACCIDX[NQ] = { 0, 1, 2, 3, 4, 5, 6, 5, 6, 5, 6, 5 };
    constexpr int LMASK[NQ]  = { 0x15, 0x1F, 0x1F, 0x1F, 0x1F, 0x1F,
                                 0x1F, 0x1E, 0x1D, 0x1A, 0x15, 0x0A };
    float e[NQ];
#pragma unroll
    for (int q = 0; q < NQ; q++) {
        float v = acc[ACCIDX[q]];
        e[q] = (__popc(lane & LMASK[q]) & 1) ? -v : v;
    }
#pragma unroll
    for (int q = 0; q < NQ; q++) {
#pragma unroll
        for (int off = 16; off > 0; off >>= 1)
            e[q] += __shfl_xor_sync(FULLMASK, e[q], off);
    }

    if (lane == 0) {
        float4* o = (float4*)(out + b * NQ);
        o[0] = make_float4(e[0], e[1], e[2],  e[3]);
        o[1] = make_float4(e[4], e[5], e[6],  e[7]);
        o[2] = make_float4(e[8], e[9], e[10], e[11]);
    }
}

extern "C" void kernel_launch(void* const* d_in, const int* in_sizes, int n_in,
                              void* d_out, int out_size)
{
    const float* x  = (const float*)d_in[0];   // (1024, 12) f32
    const float* th = (const float*)d_in[1];   // (2, 12)   f32
    float* out = (float*)d_out;                // (1024, 12) f32

    // 1 warp per batch element, 1 warp per block for near-perfect wave balance
    qcircuit_kernel<<<BATCH, 32>>>(x, th, out);
}